// round 4
// baseline (speedup 1.0000x reference)
#include <cuda_runtime.h>
#include <cuda_bf16.h>
#include <cstdint>

#define BATCH 2048
#define NCLS  1000
#define DIM   128
#define TM 128
#define TN 128
#define ROWB 272            // smem row stride: 128 bf16 + 16B pad (conflict-free)
#define NCTA 128

// deterministic likelihood partials (one per CTA) + completion ticket
__device__ __align__(16) float g_part[NCTA];
__device__ int g_ticket;

// ---- smem byte offsets ----
#define OFF_A   0                       // A tile: 128 rows x 272B = 34816
#define OFF_B   (128 * ROWB)            // B tile: 34816
#define OFF_FNP (256 * ROWB)            // float[128][2] feat norm partials
#define OFF_CNP (OFF_FNP + 1024)        // float[128][2] center norm partials
#define OFF_FNC (OFF_CNP + 1024)        // float[128]  0.5*||f||^2
#define OFF_CNC (OFF_FNC + 512)         // float[128]  0.5*||c||^2
#define OFF_RED (OFF_CNC + 512)         // float[8] warp partials
#define SMEM_BYTES (OFF_RED + 64)

static __device__ __forceinline__ uint32_t smem_u32(const void* p) {
    uint32_t a;
    asm("{ .reg .u64 t; cvta.to.shared.u64 t, %1; cvt.u32.u64 %0, t; }"
        : "=r"(a) : "l"(p));
    return a;
}

static __device__ __forceinline__ int get_label(const void* lab, int b, int is64) {
    if (is64) return (int)(((const long long*)lab)[b]);
    return ((const int*)lab)[b];
}

static __device__ __forceinline__ uint32_t bf2(float x, float y) {
    __nv_bfloat162 v = __floats2bfloat162_rn(x, y);
    return *(uint32_t*)&v;
}

#define LDSM_X4(d, addr)                                                        \
    asm volatile("ldmatrix.sync.aligned.m8n8.x4.shared.b16 {%0,%1,%2,%3},[%4];" \
        : "=r"((d)[0]), "=r"((d)[1]), "=r"((d)[2]), "=r"((d)[3])                \
        : "r"(addr))

#define MMA16816(d, a, b0, b1)                                                  \
    asm volatile("mma.sync.aligned.m16n8k16.row.col.f32.bf16.bf16.f32 "         \
        "{%0,%1,%2,%3}, {%4,%5,%6,%7}, {%8,%9}, {%0,%1,%2,%3};"                 \
        : "+f"((d)[0]), "+f"((d)[1]), "+f"((d)[2]), "+f"((d)[3])                \
        : "r"((a)[0]), "r"((a)[1]), "r"((a)[2]), "r"((a)[3]),                   \
          "r"(b0), "r"(b1))

__global__ void __launch_bounds__(256, 1)
lgm_mma_kernel(const float* __restrict__ feat,
               const void*  __restrict__ label,
               const float* __restrict__ centers,
               float* __restrict__ logits,
               float* __restrict__ mlogits,
               float* __restrict__ lik)
{
    extern __shared__ char smem[];
    const uint32_t sb = smem_u32(smem);
    const int tid = threadIdx.x;
    const int bb = blockIdx.y * TM;
    const int cc = blockIdx.x * TN;

    // ---------------- staging: f32 -> bf16 tiles + fused norms ----------------
    const int r = tid & 127;     // tile row
    const int h = tid >> 7;      // which 64-col half

    {   // A = feat (always in-bounds): batch all 16 LDG.128 first (MLP=16)
        const float4* src = (const float4*)(feat + (size_t)(bb + r) * DIM + h * 64);
        float4 v[16];
#pragma unroll
        for (int j = 0; j < 16; j++) v[j] = src[j];
        char* dst = smem + OFF_A + r * ROWB + h * 128;
        float s = 0.f;
#pragma unroll
        for (int j = 0; j < 8; j++) {
            float4 v0 = v[2 * j], v1 = v[2 * j + 1];
            s += v0.x * v0.x + v0.y * v0.y + v0.z * v0.z + v0.w * v0.w
               + v1.x * v1.x + v1.y * v1.y + v1.z * v1.z + v1.w * v1.w;
            uint4 p;
            p.x = bf2(v0.x, v0.y);
            p.y = bf2(v0.z, v0.w);
            p.z = bf2(v1.x, v1.y);
            p.w = bf2(v1.z, v1.w);
            *(uint4*)(dst + j * 16) = p;
        }
        ((float*)(smem + OFF_FNP))[r * 2 + h] = s;
    }
    {   // B = centers (zero-fill rows >= NCLS)
        const int crow = cc + r;
        const bool ok = crow < NCLS;
        const float4* src = (const float4*)(centers + (size_t)crow * DIM + h * 64);
        float4 v[16];
#pragma unroll
        for (int j = 0; j < 16; j++)
            v[j] = ok ? src[j] : make_float4(0.f, 0.f, 0.f, 0.f);
        char* dst = smem + OFF_B + r * ROWB + h * 128;
        float s = 0.f;
#pragma unroll
        for (int j = 0; j < 8; j++) {
            float4 v0 = v[2 * j], v1 = v[2 * j + 1];
            s += v0.x * v0.x + v0.y * v0.y + v0.z * v0.z + v0.w * v0.w
               + v1.x * v1.x + v1.y * v1.y + v1.z * v1.z + v1.w * v1.w;
            uint4 p;
            p.x = bf2(v0.x, v0.y);
            p.y = bf2(v0.z, v0.w);
            p.z = bf2(v1.x, v1.y);
            p.w = bf2(v1.z, v1.w);
            *(uint4*)(dst + j * 16) = p;
        }
        ((float*)(smem + OFF_CNP))[r * 2 + h] = s;
    }

    // label dtype probe on global rows 0..127 ONLY (in-bounds for int32 too):
    // int64 labels < 1000  =>  all sampled high words zero
    int hw = 0;
    if (tid < 128) hw = (((const int*)label)[2 * tid + 1] != 0);
    const int is64 = !__syncthreads_or(hw);    // barrier also covers smem stores

    if (tid < 128) {
        const float* fnp = (const float*)(smem + OFF_FNP);
        const float* cnp = (const float*)(smem + OFF_CNP);
        ((float*)(smem + OFF_FNC))[tid] = 0.5f * (fnp[2 * tid] + fnp[2 * tid + 1]);
        ((float*)(smem + OFF_CNC))[tid] = 0.5f * (cnp[2 * tid] + cnp[2 * tid + 1]);
    }
    __syncthreads();

    // ---------------- HMMA mainloop ----------------
    const int wid  = tid >> 5;
    const int lane = tid & 31;
    const int wm = wid & 3;          // M group: rows wm*32..+31
    const int wn = wid >> 2;         // N group: cols wn*64..+63

    // ldmatrix lane addressing (same scheme for A and B, both k-contiguous):
    // row = base + (lane & 15), 16B k-chunk = (lane >> 4)
    const uint32_t la  = sb + OFF_A + (wm * 32 + (lane & 15)) * ROWB + (lane >> 4) * 16;
    const uint32_t lbm = sb + OFF_B + (wn * 64 + (lane & 15)) * ROWB + (lane >> 4) * 16;

    float acc[2][8][4] = {};
#pragma unroll
    for (int ks = 0; ks < 8; ks++) {
        const uint32_t ko = ks * 32;
        uint32_t a[2][4], b[4][4];
        LDSM_X4(a[0], la + ko);
        LDSM_X4(a[1], la + 16 * ROWB + ko);
#pragma unroll
        for (int nb = 0; nb < 4; nb++) LDSM_X4(b[nb], lbm + nb * 16 * ROWB + ko);
#pragma unroll
        for (int mi = 0; mi < 2; mi++)
#pragma unroll
            for (int nb = 0; nb < 4; nb++) {
                MMA16816(acc[mi][nb * 2 + 0], a[mi], b[nb][0], b[nb][2]);
                MMA16816(acc[mi][nb * 2 + 1], a[mi], b[nb][1], b[nb][3]);
            }
    }

    // ---------------- epilogue ----------------
    // D frag: {d0,d1}=row g cols tc*2..+1, {d2,d3}=row g+8
    const int g  = lane >> 2;
    const int tc = lane & 3;
    const float* fnc = (const float*)(smem + OFF_FNC);
    const float* cnc = (const float*)(smem + OFF_CNC);

    float lacc = 0.f;
#pragma unroll
    for (int mi = 0; mi < 2; mi++) {
#pragma unroll
        for (int rr = 0; rr < 2; rr++) {
            const int rloc = wm * 32 + mi * 16 + g + rr * 8;
            const int m = bb + rloc;
            const float fnh = fnc[rloc];
            const int lb = get_label(label, m, is64);
#pragma unroll
            for (int nf = 0; nf < 8; nf++) {
                const int cloc = wn * 64 + (nf >> 1) * 16 + (nf & 1) * 8 + tc * 2;
                const int c = cc + cloc;
                const float d0 = acc[mi][nf][rr * 2 + 0];
                const float d1 = acc[mi][nf][rr * 2 + 1];
                // logits = -0.5*dist = dot - 0.5||f||^2 - 0.5||c||^2
                const float lg0 = d0 - fnh - cnc[cloc];
                const float lg1 = d1 - fnh - cnc[cloc + 1];
                float ml0 = lg0, ml1 = lg1;
                if (lb == c)     { ml0 = 2.f * lg0; lacc += lg0; }
                if (lb == c + 1) { ml1 = 2.f * lg1; lacc += lg1; }
                if (c < NCLS) {
                    const size_t off = (size_t)m * NCLS + c;
                    *(float2*)(logits + off)  = make_float2(lg0, lg1);
                    *(float2*)(mlogits + off) = make_float2(ml0, ml1);
                }
            }
        }
    }

    // ---------------- likelihood: warp reduce -> CTA partial -> last CTA ------
#pragma unroll
    for (int o = 16; o > 0; o >>= 1)
        lacc += __shfl_xor_sync(0xffffffffu, lacc, o);
    float* red = (float*)(smem + OFF_RED);
    if (lane == 0) red[wid] = lacc;
    __syncthreads();

    if (tid == 0) {
        float s = red[0] + red[1] + red[2] + red[3]
                + red[4] + red[5] + red[6] + red[7];
        const int bid = blockIdx.y * 8 + blockIdx.x;
        g_part[bid] = s;
        __threadfence();
        int t = atomicAdd(&g_ticket, 1);
        if (t == NCTA - 1) {
            __threadfence();
            // fixed-order, fixed-split sum => deterministic
            float a0 = 0.f, a1 = 0.f, a2 = 0.f, a3 = 0.f;
            const float4* p4 = (const float4*)g_part;
#pragma unroll
            for (int i = 0; i < NCTA / 4; i++) {
                float4 v = p4[i];
                a0 += v.x; a1 += v.y; a2 += v.z; a3 += v.w;
            }
            *lik = -((a0 + a1) + (a2 + a3)) * (1.f / (float)BATCH);
            g_ticket = 0;          // reset for next graph replay
        }
    }
}

extern "C" void kernel_launch(void* const* d_in, const int* in_sizes, int n_in,
                              void* d_out, int out_size) {
    const float* feat    = (const float*)d_in[0];
    const void*  label   = d_in[1];
    const float* centers = (const float*)d_in[2];

    float* out     = (float*)d_out;
    float* logits  = out;                              // [B, C]
    float* mlogits = out + (size_t)BATCH * NCLS;       // [B, C]
    float* lik     = out + 2 * (size_t)BATCH * NCLS;   // scalar

    cudaFuncSetAttribute(lgm_mma_kernel,
                         cudaFuncAttributeMaxDynamicSharedMemorySize, SMEM_BYTES);

    dim3 grid(8, 16);   // 128 CTAs, one wave
    lgm_mma_kernel<<<grid, 256, SMEM_BYTES>>>(feat, label, centers,
                                              logits, mlogits, lik);
}